// round 6
// baseline (speedup 1.0000x reference)
#include <cuda_runtime.h>
#include <cuda_bf16.h>
#include <math.h>

// Problem constants (from reference): N=500000, E=16000000, IN_DIM=17
#define NMAX 500000
#define IN_DIM 17

// Scratch (allocation-free rule: __device__ globals)
__device__ float2 g_accum[NMAX];   // interleaved {sum, count} per node
__device__ float  g_projl[NMAX];   // x @ w_l^T
__device__ float  g_projr[NMAX];   // x @ w_r^T
__device__ int    g_use64;         // 1 if edge_index is int64, 0 if int32

// ---------------------------------------------------------------------------
// Kernel 0: dtype probe. JAX without x64 silently downgrades the reference's
// requested int64 edge_index to int32. Interpret the first 2048 entries as
// int64; any value outside [0, N) => data is really int32. (Random 31-bit
// index pairs reinterpreted as int64 exceed N with probability ~1.)
// ---------------------------------------------------------------------------
__global__ void k_detect(const long long* __restrict__ ei, int n) {
    int bad = 0;
    for (int i = threadIdx.x; i < 2048; i += 32) {
        long long v = ei[i];
        if (v < 0 || v >= (long long)n) bad = 1;
    }
    bad = __any_sync(0xFFFFFFFFu, bad);
    if (threadIdx.x == 0) g_use64 = bad ? 0 : 1;
}

// ---------------------------------------------------------------------------
// Kernel 1: per-node projections + zero the accumulator. 34 MB streamed.
// ---------------------------------------------------------------------------
__global__ void k_proj(const float* __restrict__ x,
                       const float* __restrict__ wl,
                       const float* __restrict__ wr,
                       int n) {
    int i = blockIdx.x * blockDim.x + threadIdx.x;
    if (i >= n) return;
    const float* xi = x + (size_t)i * IN_DIM;
    float pl = 0.f, pr = 0.f;
#pragma unroll
    for (int k = 0; k < IN_DIM; k++) {
        float v = xi[k];
        pl = fmaf(v, __ldg(&wl[k]), pl);
        pr = fmaf(v, __ldg(&wr[k]), pr);
    }
    g_projl[i] = pl;
    g_projr[i] = pr;
    g_accum[i] = make_float2(0.f, 0.f);
}

// ---------------------------------------------------------------------------
// Kernel 2: edge scatter. 8 edges/thread. One fused vector reduction per
// edge: {msg, 1.0}. Streaming loads (__ldcs) keep the 64-128 MB index
// stream out of L2 so the 2 MB gather table + 4 MB accumulator stay
// resident. red.global.add.v2.f32 halves atomic count vs scalar sum+cnt.
// ---------------------------------------------------------------------------
#define EPT 8   // edges per thread

__device__ __forceinline__ void red_add_v2(float2* addr, float a, float b) {
    asm volatile("red.global.add.v2.f32 [%0], {%1, %2};"
                 :: "l"(addr), "f"(a), "f"(b) : "memory");
}

__global__ void k_edge(const void* __restrict__ ei_raw, long long E, int n) {
    long long base = (long long)EPT * ((long long)blockIdx.x * blockDim.x + threadIdx.x);
    if (base >= E) return;

    long long s[EPT], d[EPT];
    int cnt;
    if (base + EPT <= E) {
        cnt = EPT;
        if (g_use64) {
            const long long* p = (const long long*)ei_raw;
#pragma unroll
            for (int j = 0; j < EPT; j += 2) {
                longlong2 sv = __ldcs((const longlong2*)(p + base + j));
                longlong2 dv = __ldcs((const longlong2*)(p + E + base + j));
                s[j] = sv.x; s[j + 1] = sv.y;
                d[j] = dv.x; d[j + 1] = dv.y;
            }
        } else {
            const int* p = (const int*)ei_raw;
#pragma unroll
            for (int j = 0; j < EPT; j += 4) {
                int4 sv = __ldcs((const int4*)(p + base + j));
                int4 dv = __ldcs((const int4*)(p + E + base + j));
                s[j] = sv.x; s[j + 1] = sv.y; s[j + 2] = sv.z; s[j + 3] = sv.w;
                d[j] = dv.x; d[j + 1] = dv.y; d[j + 2] = dv.z; d[j + 3] = dv.w;
            }
        }
    } else {
        cnt = (int)(E - base);
        if (g_use64) {
            const long long* p = (const long long*)ei_raw;
            for (int j = 0; j < cnt; j++) {
                s[j] = __ldcs(p + base + j);
                d[j] = __ldcs(p + E + base + j);
            }
        } else {
            const int* p = (const int*)ei_raw;
            for (int j = 0; j < cnt; j++) {
                s[j] = __ldcs(p + base + j);
                d[j] = __ldcs(p + E + base + j);
            }
        }
    }

#pragma unroll
    for (int j = 0; j < EPT; j++) {
        if (j < cnt) {
            // Range guard: a wrong dtype guess fails with rel_err, not IMA.
            if ((unsigned long long)s[j] < (unsigned long long)n &&
                (unsigned long long)d[j] < (unsigned long long)n) {
                red_add_v2(&g_accum[d[j]], g_projl[s[j]], 1.0f);
            }
        }
    }
}

// ---------------------------------------------------------------------------
// Kernel 3: finalize. mean -> lin_l + lin_r -> elu -> out linear.
// ---------------------------------------------------------------------------
__global__ void k_final(float* __restrict__ out,
                        const float* __restrict__ bl,
                        const float* __restrict__ wo,
                        const float* __restrict__ bo,
                        int n) {
    int i = blockIdx.x * blockDim.x + threadIdx.x;
    if (i >= n) return;
    float2 ac = g_accum[i];
    float mean = ac.x / fmaxf(ac.y, 1.0f);
    float h = mean + __ldg(&bl[0]) + g_projr[i];
    h = (h > 0.f) ? h : expm1f(h);          // elu, alpha=1
    out[i] = fmaf(h, __ldg(&wo[0]), __ldg(&bo[0]));
}

// ---------------------------------------------------------------------------
// Inputs (metadata order): x[N*17] f32, edge_index[2*E] int (width probed),
// edge_weight[E] f32 (UNUSED, faithful to PyG SAGEConv), w_l[17], b_l[1],
// w_r[17], w_o[1], b_o[1]. Output: [N] f32.
// ---------------------------------------------------------------------------
extern "C" void kernel_launch(void* const* d_in, const int* in_sizes, int n_in,
                              void* d_out, int out_size) {
    const float* x  = (const float*)d_in[0];
    const void*  ei = d_in[1];
    const float* wl = (const float*)d_in[3];
    const float* bl = (const float*)d_in[4];
    const float* wr = (const float*)d_in[5];
    const float* wo = (const float*)d_in[6];
    const float* bo = (const float*)d_in[7];
    float* out = (float*)d_out;

    int       n = in_sizes[0] / IN_DIM;
    long long E = (long long)in_sizes[1] / 2;   // element count is dtype-invariant

    const int TPB = 256;
    k_detect<<<1, 32>>>((const long long*)ei, n);
    k_proj<<<(n + TPB - 1) / TPB, TPB>>>(x, wl, wr, n);

    long long groups = (E + EPT - 1) / EPT;
    int eblocks = (int)((groups + TPB - 1) / TPB);
    k_edge<<<eblocks, TPB>>>(ei, E, n);

    k_final<<<(n + TPB - 1) / TPB, TPB>>>(out, bl, wo, bo, n);
}

// round 7
// speedup vs baseline: 1.0145x; 1.0145x over previous
#include <cuda_runtime.h>
#include <cuda_bf16.h>
#include <math.h>

// Problem constants (from reference): N=500000, E=16000000, IN_DIM=17
#define NMAX 500000
#define IN_DIM 17

// Fixed-point packing: per-edge encoded value = round(msg * 2^24) + 2^40.
// Accumulator = cnt*2^40 + sum_fixed, |sum_fixed| < 2^39 always.
#define FIX_SCALE 16777216.0f           // 2^24
#define FIX_INV   (1.0f / 16777216.0f)
#define CNT_SHIFT 40

// Scratch (allocation-free rule: __device__ globals)
__device__ unsigned long long g_accum[NMAX];  // packed {count, fixed-point sum}
__device__ float  g_projl[NMAX];              // x @ w_l^T
__device__ float  g_projr[NMAX];              // x @ w_r^T
__device__ int    g_use64;                    // 1 if edge_index is int64

// ---------------------------------------------------------------------------
// Kernel 1: per-node projections + zero accumulator + (block 0) dtype probe.
// JAX without x64 silently downgrades the requested int64 edge_index to
// int32; reinterpreting random int32 pairs as int64 exceeds [0,N) w.p. ~1.
// ---------------------------------------------------------------------------
__global__ void k_proj(const float* __restrict__ x,
                       const float* __restrict__ wl,
                       const float* __restrict__ wr,
                       const long long* __restrict__ ei,
                       int n) {
    if (blockIdx.x == 0 && threadIdx.x < 32) {
        int bad = 0;
        for (int i = threadIdx.x; i < 2048; i += 32) {
            long long v = ei[i];
            if (v < 0 || v >= (long long)n) bad = 1;
        }
        bad = __any_sync(0xFFFFFFFFu, bad);
        if (threadIdx.x == 0) g_use64 = bad ? 0 : 1;
    }
    int i = blockIdx.x * blockDim.x + threadIdx.x;
    if (i >= n) return;
    const float* xi = x + (size_t)i * IN_DIM;
    float pl = 0.f, pr = 0.f;
#pragma unroll
    for (int k = 0; k < IN_DIM; k++) {
        float v = xi[k];
        pl = fmaf(v, __ldg(&wl[k]), pl);
        pr = fmaf(v, __ldg(&wr[k]), pr);
    }
    g_projl[i] = pl;
    g_projr[i] = pr;
    g_accum[i] = 0ULL;
}

// ---------------------------------------------------------------------------
// Kernel 2: edge scatter. 8 edges/thread. ONE u64 integer reduction per edge
// (fixed-point sum + count packed) — half the LTS float-ALU work of the
// previous red.add.v2.f32. __ldcs keeps the 128-256 MB index stream out of
// L2 so the 2 MB gather table + 4 MB accumulator stay resident.
// ---------------------------------------------------------------------------
#define EPT 8

__device__ __forceinline__ void red_add_u64(unsigned long long* addr,
                                            unsigned long long v) {
    asm volatile("red.global.add.u64 [%0], %1;" :: "l"(addr), "l"(v) : "memory");
}

__global__ void k_edge(const void* __restrict__ ei_raw, long long E, int n) {
    long long base = (long long)EPT * ((long long)blockIdx.x * blockDim.x + threadIdx.x);
    if (base >= E) return;

    long long s[EPT], d[EPT];
    int cnt;
    if (base + EPT <= E) {
        cnt = EPT;
        if (g_use64) {
            const long long* p = (const long long*)ei_raw;
#pragma unroll
            for (int j = 0; j < EPT; j += 2) {
                longlong2 sv = __ldcs((const longlong2*)(p + base + j));
                longlong2 dv = __ldcs((const longlong2*)(p + E + base + j));
                s[j] = sv.x; s[j + 1] = sv.y;
                d[j] = dv.x; d[j + 1] = dv.y;
            }
        } else {
            const int* p = (const int*)ei_raw;
#pragma unroll
            for (int j = 0; j < EPT; j += 4) {
                int4 sv = __ldcs((const int4*)(p + base + j));
                int4 dv = __ldcs((const int4*)(p + E + base + j));
                s[j] = sv.x; s[j + 1] = sv.y; s[j + 2] = sv.z; s[j + 3] = sv.w;
                d[j] = dv.x; d[j + 1] = dv.y; d[j + 2] = dv.z; d[j + 3] = dv.w;
            }
        }
    } else {
        cnt = (int)(E - base);
        if (g_use64) {
            const long long* p = (const long long*)ei_raw;
            for (int j = 0; j < cnt; j++) {
                s[j] = __ldcs(p + base + j);
                d[j] = __ldcs(p + E + base + j);
            }
        } else {
            const int* p = (const int*)ei_raw;
            for (int j = 0; j < cnt; j++) {
                s[j] = __ldcs(p + base + j);
                d[j] = __ldcs(p + E + base + j);
            }
        }
    }

#pragma unroll
    for (int j = 0; j < EPT; j++) {
        if (j < cnt) {
            // Range guard: a wrong dtype guess fails with rel_err, not IMA.
            if ((unsigned long long)s[j] < (unsigned long long)n &&
                (unsigned long long)d[j] < (unsigned long long)n) {
                float msg = g_projl[s[j]];
                unsigned long long v =
                    (unsigned long long)(llrintf(msg * FIX_SCALE) + (1LL << CNT_SHIFT));
                red_add_u64(&g_accum[d[j]], v);
            }
        }
    }
}

// ---------------------------------------------------------------------------
// Kernel 3: finalize. unpack -> mean -> lin_l + lin_r -> elu -> out linear.
// ---------------------------------------------------------------------------
__global__ void k_final(float* __restrict__ out,
                        const float* __restrict__ bl,
                        const float* __restrict__ wo,
                        const float* __restrict__ bo,
                        int n) {
    int i = blockIdx.x * blockDim.x + threadIdx.x;
    if (i >= n) return;
    unsigned long long acc = g_accum[i];
    // |sum_fixed| < 2^39, so rounding by +2^39 recovers the exact count.
    long long c = (long long)((acc + (1ULL << (CNT_SHIFT - 1))) >> CNT_SHIFT);
    long long sumfix = (long long)acc - (c << CNT_SHIFT);
    float sum = (float)sumfix * FIX_INV;
    float mean = sum / fmaxf((float)c, 1.0f);
    float h = mean + __ldg(&bl[0]) + g_projr[i];
    h = (h > 0.f) ? h : expm1f(h);          // elu, alpha=1
    out[i] = fmaf(h, __ldg(&wo[0]), __ldg(&bo[0]));
}

// ---------------------------------------------------------------------------
// Inputs (metadata order): x[N*17] f32, edge_index[2*E] int (width probed),
// edge_weight[E] f32 (UNUSED, faithful to PyG SAGEConv), w_l[17], b_l[1],
// w_r[17], w_o[1], b_o[1]. Output: [N] f32.
// ---------------------------------------------------------------------------
extern "C" void kernel_launch(void* const* d_in, const int* in_sizes, int n_in,
                              void* d_out, int out_size) {
    const float* x  = (const float*)d_in[0];
    const void*  ei = d_in[1];
    const float* wl = (const float*)d_in[3];
    const float* bl = (const float*)d_in[4];
    const float* wr = (const float*)d_in[5];
    const float* wo = (const float*)d_in[6];
    const float* bo = (const float*)d_in[7];
    float* out = (float*)d_out;

    int       n = in_sizes[0] / IN_DIM;
    long long E = (long long)in_sizes[1] / 2;   // element count is dtype-invariant

    const int TPB = 256;
    k_proj<<<(n + TPB - 1) / TPB, TPB>>>(x, wl, wr, (const long long*)ei, n);

    long long groups = (E + EPT - 1) / EPT;
    int eblocks = (int)((groups + TPB - 1) / TPB);
    k_edge<<<eblocks, TPB>>>(ei, E, n);

    k_final<<<(n + TPB - 1) / TPB, TPB>>>(out, bl, wo, bo, n);
}

// round 8
// speedup vs baseline: 1.2567x; 1.2387x over previous
#include <cuda_runtime.h>
#include <cuda_bf16.h>
#include <math.h>

// Problem constants (from reference): N=500000, E=16000000, IN_DIM=17
#define NMAX 500000
#define IN_DIM 17

// Fixed-point packing: per-edge encoded value = round(msg * 2^24) + 2^40.
// Accumulator = cnt*2^40 + sum_fixed, |sum_fixed| < 2^39 always.
#define FIX_SCALE 16777216.0f           // 2^24
#define FIX_INV   (1.0f / 16777216.0f)
#define CNT_SHIFT 40

// Scratch (allocation-free rule: __device__ globals)
__device__ unsigned long long g_accum[NMAX];  // packed {count, fixed-point sum}
__device__ float  g_projl[NMAX];              // x @ w_l^T
__device__ float  g_projr[NMAX];              // x @ w_r^T
__device__ int    g_use64;                    // 1 if edge_index is int64

// ---------------------------------------------------------------------------
// Kernel 1: per-node projections + zero accumulator + (block 0) dtype probe.
// JAX without x64 silently downgrades the requested int64 edge_index to
// int32; reinterpreting random int32 pairs as int64 exceeds [0,N) w.p. ~1.
// ---------------------------------------------------------------------------
__global__ void k_proj(const float* __restrict__ x,
                       const float* __restrict__ wl,
                       const float* __restrict__ wr,
                       const long long* __restrict__ ei,
                       int n) {
    if (blockIdx.x == 0 && threadIdx.x < 32) {
        int bad = 0;
        for (int i = threadIdx.x; i < 2048; i += 32) {
            long long v = ei[i];
            if (v < 0 || v >= (long long)n) bad = 1;
        }
        bad = __any_sync(0xFFFFFFFFu, bad);
        if (threadIdx.x == 0) g_use64 = bad ? 0 : 1;
    }
    int i = blockIdx.x * blockDim.x + threadIdx.x;
    if (i >= n) return;
    const float* xi = x + (size_t)i * IN_DIM;
    float pl = 0.f, pr = 0.f;
#pragma unroll
    for (int k = 0; k < IN_DIM; k++) {
        float v = xi[k];
        pl = fmaf(v, __ldg(&wl[k]), pl);
        pr = fmaf(v, __ldg(&wr[k]), pr);
    }
    g_projl[i] = pl;
    g_projr[i] = pr;
    g_accum[i] = 0ULL;
}

// ---------------------------------------------------------------------------
// Kernel 2: edge scatter. 8 edges/thread.
// Phase order maximizes MLP: (1) vector-load 8 src + 8 dst indices,
// (2) issue ALL 8 gathers of proj_l (8 independent LDGs in flight),
// (3) fire 8 fire-and-forget u64 REDs (packed fixed-point sum + count).
// The bound is L1tex wavefronts from lane divergence (~1 line per lane on
// both gather and RED); front-batching hides the L2 gather latency under
// that throughput floor. __ldcs keeps the index stream out of L2.
// ---------------------------------------------------------------------------
#define EPT 8

__device__ __forceinline__ void red_add_u64(unsigned long long* addr,
                                            unsigned long long v) {
    asm volatile("red.global.add.u64 [%0], %1;" :: "l"(addr), "l"(v) : "memory");
}

__device__ __forceinline__ unsigned long long pack_msg(float msg) {
    return (unsigned long long)(llrintf(msg * FIX_SCALE) + (1LL << CNT_SHIFT));
}

__global__ void k_edge(const void* __restrict__ ei_raw, long long E, int n) {
    long long base = (long long)EPT * ((long long)blockIdx.x * blockDim.x + threadIdx.x);
    if (base >= E) return;

    if (!g_use64) {
        // ---- int32 fast path (expected) ----
        const int* p = (const int*)ei_raw;
        int s[EPT], d[EPT];
        if (base + EPT <= E) {
#pragma unroll
            for (int j = 0; j < EPT; j += 4) {
                int4 sv = __ldcs((const int4*)(p + base + j));
                s[j] = sv.x; s[j + 1] = sv.y; s[j + 2] = sv.z; s[j + 3] = sv.w;
            }
#pragma unroll
            for (int j = 0; j < EPT; j += 4) {
                int4 dv = __ldcs((const int4*)(p + E + base + j));
                d[j] = dv.x; d[j + 1] = dv.y; d[j + 2] = dv.z; d[j + 3] = dv.w;
            }
            // Front-batch all gathers (guards keep a wrong dtype guess from IMA)
            float m[EPT];
            bool ok[EPT];
#pragma unroll
            for (int j = 0; j < EPT; j++) {
                ok[j] = (unsigned)s[j] < (unsigned)n && (unsigned)d[j] < (unsigned)n;
                m[j] = ok[j] ? g_projl[s[j]] : 0.f;
            }
#pragma unroll
            for (int j = 0; j < EPT; j++)
                if (ok[j]) red_add_u64(&g_accum[d[j]], pack_msg(m[j]));
        } else {
            int cnt = (int)(E - base);
            for (int j = 0; j < cnt; j++) {
                int sj = __ldcs(p + base + j);
                int dj = __ldcs(p + E + base + j);
                if ((unsigned)sj < (unsigned)n && (unsigned)dj < (unsigned)n)
                    red_add_u64(&g_accum[dj], pack_msg(g_projl[sj]));
            }
        }
    } else {
        // ---- int64 path ----
        const long long* p = (const long long*)ei_raw;
        long long s[EPT], d[EPT];
        int cnt = (int)((base + EPT <= E) ? EPT : (E - base));
        if (cnt == EPT) {
#pragma unroll
            for (int j = 0; j < EPT; j += 2) {
                longlong2 sv = __ldcs((const longlong2*)(p + base + j));
                s[j] = sv.x; s[j + 1] = sv.y;
            }
#pragma unroll
            for (int j = 0; j < EPT; j += 2) {
                longlong2 dv = __ldcs((const longlong2*)(p + E + base + j));
                d[j] = dv.x; d[j + 1] = dv.y;
            }
        } else {
            for (int j = 0; j < cnt; j++) {
                s[j] = __ldcs(p + base + j);
                d[j] = __ldcs(p + E + base + j);
            }
        }
        float m[EPT];
        bool ok[EPT];
#pragma unroll
        for (int j = 0; j < EPT; j++) {
            ok[j] = (j < cnt) &&
                    (unsigned long long)s[j] < (unsigned long long)n &&
                    (unsigned long long)d[j] < (unsigned long long)n;
            m[j] = ok[j] ? g_projl[s[j]] : 0.f;
        }
#pragma unroll
        for (int j = 0; j < EPT; j++)
            if (ok[j]) red_add_u64(&g_accum[d[j]], pack_msg(m[j]));
    }
}

// ---------------------------------------------------------------------------
// Kernel 3: finalize. unpack -> mean -> lin_l + lin_r -> elu -> out linear.
// ---------------------------------------------------------------------------
__global__ void k_final(float* __restrict__ out,
                        const float* __restrict__ bl,
                        const float* __restrict__ wo,
                        const float* __restrict__ bo,
                        int n) {
    int i = blockIdx.x * blockDim.x + threadIdx.x;
    if (i >= n) return;
    unsigned long long acc = g_accum[i];
    // |sum_fixed| < 2^39, so rounding by +2^39 recovers the exact count.
    long long c = (long long)((acc + (1ULL << (CNT_SHIFT - 1))) >> CNT_SHIFT);
    long long sumfix = (long long)acc - (c << CNT_SHIFT);
    float sum = (float)sumfix * FIX_INV;
    float mean = sum / fmaxf((float)c, 1.0f);
    float h = mean + __ldg(&bl[0]) + g_projr[i];
    h = (h > 0.f) ? h : expm1f(h);          // elu, alpha=1
    out[i] = fmaf(h, __ldg(&wo[0]), __ldg(&bo[0]));
}

// ---------------------------------------------------------------------------
// Inputs (metadata order): x[N*17] f32, edge_index[2*E] int (width probed),
// edge_weight[E] f32 (UNUSED, faithful to PyG SAGEConv), w_l[17], b_l[1],
// w_r[17], w_o[1], b_o[1]. Output: [N] f32.
// ---------------------------------------------------------------------------
extern "C" void kernel_launch(void* const* d_in, const int* in_sizes, int n_in,
                              void* d_out, int out_size) {
    const float* x  = (const float*)d_in[0];
    const void*  ei = d_in[1];
    const float* wl = (const float*)d_in[3];
    const float* bl = (const float*)d_in[4];
    const float* wr = (const float*)d_in[5];
    const float* wo = (const float*)d_in[6];
    const float* bo = (const float*)d_in[7];
    float* out = (float*)d_out;

    int       n = in_sizes[0] / IN_DIM;
    long long E = (long long)in_sizes[1] / 2;   // element count is dtype-invariant

    const int TPB = 256;
    k_proj<<<(n + TPB - 1) / TPB, TPB>>>(x, wl, wr, (const long long*)ei, n);

    long long groups = (E + EPT - 1) / EPT;
    int eblocks = (int)((groups + TPB - 1) / TPB);
    k_edge<<<eblocks, TPB>>>(ei, E, n);

    k_final<<<(n + TPB - 1) / TPB, TPB>>>(out, bl, wo, bo, n);
}